// round 11
// baseline (speedup 1.0000x reference)
#include <cuda_runtime.h>

#define TPB 52         // 4 bl-groups * 13 nodes; each thread does 4 batch elems
#define NB  16         // batch elems per block
#define NS  4          // streams per thread
#define NGRID 2048     // 32768 / 16

#define ARENA_BYTES 3536
#define WREG_BYTES  16912
#define SMEM_TOTAL  (WREG_BYTES + NB * ARENA_BYTES)   // 73488 -> 3 CTAs/SM

// packed f32x2 FMA (sm_100+): r = a*b + c per 32-bit half
__device__ __forceinline__ float2 ffma2(float2 a, float2 b, float2 c) {
    unsigned long long ua = *reinterpret_cast<unsigned long long*>(&a);
    unsigned long long ub = *reinterpret_cast<unsigned long long*>(&b);
    unsigned long long uc = *reinterpret_cast<unsigned long long*>(&c);
    unsigned long long ur;
    asm("fma.rn.f32x2 %0, %1, %2, %3;" : "=l"(ur) : "l"(ua), "l"(ub), "l"(uc));
    return *reinterpret_cast<float2*>(&ur);
}

__device__ __forceinline__ float2 lo2(float4 v) { return make_float2(v.x, v.y); }
__device__ __forceinline__ float2 hi2(float4 v) { return make_float2(v.z, v.w); }

__device__ __forceinline__ float getf2(const float2* v, int d) {
    return (d & 1) ? v[d >> 1].y : v[d >> 1].x;
}

__device__ __forceinline__ float lky(float v) { return fmaxf(v, 0.01f * v); }

// quad 16x16 matmul: one weight read feeds FOUR accumulator streams
__device__ __forceinline__ void mm16q(float2 o[NS][8], const float2 in[NS][8],
                                      const float4* Wq) {
#pragma unroll
    for (int d = 0; d < 16; d++) {
        float4 q0 = Wq[d * 4 + 0];
        float4 q1 = Wq[d * 4 + 1];
        float4 q2 = Wq[d * 4 + 2];
        float4 q3 = Wq[d * 4 + 3];
#pragma unroll
        for (int s = 0; s < NS; s++) {
            float a = getf2(in[s], d);
            float2 ap = make_float2(a, a);
            o[s][0] = ffma2(ap, lo2(q0), o[s][0]);
            o[s][1] = ffma2(ap, hi2(q0), o[s][1]);
            o[s][2] = ffma2(ap, lo2(q1), o[s][2]);
            o[s][3] = ffma2(ap, hi2(q1), o[s][3]);
            o[s][4] = ffma2(ap, lo2(q2), o[s][4]);
            o[s][5] = ffma2(ap, hi2(q2), o[s][5]);
            o[s][6] = ffma2(ap, lo2(q3), o[s][6]);
            o[s][7] = ffma2(ap, hi2(q3), o[s][7]);
        }
    }
}

__device__ __forceinline__ void load8s(float2* dst, const float4* src) {
    float4 c0 = src[0], c1 = src[1], c2 = src[2], c3 = src[3];
    dst[0] = lo2(c0); dst[1] = hi2(c0); dst[2] = lo2(c1); dst[3] = hi2(c1);
    dst[4] = lo2(c2); dst[5] = hi2(c2); dst[6] = lo2(c3); dst[7] = hi2(c3);
}

__global__ __launch_bounds__(TPB, 3)
void vae_kernel(
    const float* __restrict__ adj,          // (B,4,13,13)
    const float* __restrict__ init_weight,  // (13,16)
    const float* __restrict__ eps_param,    // (4)
    const float* __restrict__ mlp_w0,       // (4,16,16)
    const float* __restrict__ mlp_b0,       // (4,16)
    const float* __restrict__ mlp_w1,       // (4,16,16)
    const float* __restrict__ mlp_b1,       // (4,16)
    const float* __restrict__ bn_in_gamma,  // (4,13)
    const float* __restrict__ bn_in_beta,
    const float* __restrict__ bn_in_mean,
    const float* __restrict__ bn_in_var,
    const float* __restrict__ bn_out_gamma,
    const float* __restrict__ bn_out_beta,
    const float* __restrict__ bn_out_mean,
    const float* __restrict__ bn_out_var,
    const float* __restrict__ fc1_w,        // (16,16)
    const float* __restrict__ fc1_b,        // (16)
    const float* __restrict__ fc2_w,
    const float* __restrict__ fc2_b,
    const float* __restrict__ dec_w,        // (4,16,16)
    const float* __restrict__ dec_b,        // (4,16)
    float* __restrict__ d_out)
{
    extern __shared__ char sm[];
    float4* w0q   = (float4*)(sm + 0);      // [4][16][4]
    float4* w1q   = (float4*)(sm + 4096);   // [4][16][4]
    float4* decq  = (float4*)(sm + 8192);   // [4][16][4]
    float4* fc1q  = (float4*)(sm + 12288);  // [16][4]
    float4* fc2q  = (float4*)(sm + 13312);  // [16][4]
    float4* b0q   = (float4*)(sm + 14336);  // [4][4]
    float4* b1q   = (float4*)(sm + 14592);  // [4][4]
    float4* decbq = (float4*)(sm + 14848);  // [4][4]
    float4* fc1bq = (float4*)(sm + 15104);  // [4]
    float4* fc2bq = (float4*)(sm + 15168);  // [4]
    float2* bninq = (float2*)(sm + 15232);  // [4][13] (s,t)
    float2* bnoutq= (float2*)(sm + 15648);  // [4][13] (s,t)
    float4* winitq= (float4*)(sm + 16064);  // [13][4]
    float*  eps1  = (float*)(sm + 16896);   // [4]
    char*   arenas = sm + WREG_BYTES;

    const int t = threadIdx.x;

    // ---- stage transposed/packed weights ----
    for (int idx = t; idx < 256; idx += TPB) {          // 4*16*4
        int l = idx >> 6, d = (idx >> 2) & 15, q = idx & 3;
        const float* w  = mlp_w0 + l * 256;
        const float* w1 = mlp_w1 + l * 256;
        const float* dw = dec_w  + l * 256;
        w0q[idx]  = make_float4(w [(4*q+0)*16+d], w [(4*q+1)*16+d], w [(4*q+2)*16+d], w [(4*q+3)*16+d]);
        w1q[idx]  = make_float4(w1[(4*q+0)*16+d], w1[(4*q+1)*16+d], w1[(4*q+2)*16+d], w1[(4*q+3)*16+d]);
        decq[idx] = make_float4(dw[(4*q+0)*16+d], dw[(4*q+1)*16+d], dw[(4*q+2)*16+d], dw[(4*q+3)*16+d]);
    }
    for (int idx = t; idx < 64; idx += TPB) {           // 16*4
        int d = idx >> 2, q = idx & 3;
        fc1q[idx] = make_float4(fc1_w[(4*q+0)*16+d], fc1_w[(4*q+1)*16+d], fc1_w[(4*q+2)*16+d], fc1_w[(4*q+3)*16+d]);
        fc2q[idx] = make_float4(fc2_w[(4*q+0)*16+d], fc2_w[(4*q+1)*16+d], fc2_w[(4*q+2)*16+d], fc2_w[(4*q+3)*16+d]);
    }
    for (int idx = t; idx < 52; idx += TPB)             // 13*4
        winitq[idx] = ((const float4*)init_weight)[idx];
    for (int idx = t; idx < 16; idx += TPB) {           // 4*4
        b0q[idx]   = ((const float4*)mlp_b0)[idx];
        b1q[idx]   = ((const float4*)mlp_b1)[idx];
        decbq[idx] = ((const float4*)dec_b)[idx];
    }
    if (t < 4) {
        fc1bq[t] = ((const float4*)fc1_b)[t];
        fc2bq[t] = ((const float4*)fc2_b)[t];
        eps1[t]  = 1.0f + eps_param[t];
    }
    for (int idx = t; idx < 52; idx += TPB) {           // 4*13 BN fold
        float s = bn_in_gamma[idx] * rsqrtf(bn_in_var[idx] + 1e-5f);
        bninq[idx] = make_float2(s, bn_in_beta[idx] - bn_in_mean[idx] * s);
        float so = bn_out_gamma[idx] * rsqrtf(bn_out_var[idx] + 1e-5f);
        bnoutq[idx] = make_float2(so, bn_out_beta[idx] - bn_out_mean[idx] * so);
    }

    // ---- load adj (coalesced float4) into per-b arenas ----
    const float4* adjg = (const float4*)(adj + (size_t)blockIdx.x * NB * 676);
    for (int i = t; i < NB * 169; i += TPB) {           // 52 iters exactly
        int b = i / 169, q = i - b * 169;
        *(float4*)(arenas + b * ARENA_BYTES + q * 16) = adjg[i];
    }
    __syncthreads();

    // ---- per-thread: (bl, n) handles arenas bl, bl+4, bl+8, bl+12 ----
    const int bl = t / 13;
    const int n  = t - bl * 13;
    float*  adjS[NS];
    float4* xS[NS];
    char*   arS[NS];
#pragma unroll
    for (int s = 0; s < NS; s++) {
        arS[s]  = arenas + (bl + 4 * s) * ARENA_BYTES;
        adjS[s] = (float*)arS[s];              // [g*169 + n*13 + m]
        xS[s]   = (float4*)(arS[s] + 2704);    // [13][4] single buffer
    }

    // ---- x init ----
    float2 x2[NS][8];
#pragma unroll
    for (int s = 0; s < NS; s++)
#pragma unroll
        for (int j = 0; j < 8; j++) x2[s][j] = make_float2(0.f, 0.f);
#pragma unroll
    for (int m = 0; m < 13; m++) {
        int o = n * 13 + m;
        float4 q0 = winitq[m*4+0], q1 = winitq[m*4+1], q2 = winitq[m*4+2], q3 = winitq[m*4+3];
#pragma unroll
        for (int s = 0; s < NS; s++) {
            float sa = adjS[s][o] + adjS[s][169 + o] + adjS[s][338 + o] + adjS[s][507 + o];
            float2 ap = make_float2(sa, sa);
            x2[s][0] = ffma2(ap, lo2(q0), x2[s][0]);
            x2[s][1] = ffma2(ap, hi2(q0), x2[s][1]);
            x2[s][2] = ffma2(ap, lo2(q1), x2[s][2]);
            x2[s][3] = ffma2(ap, hi2(q1), x2[s][3]);
            x2[s][4] = ffma2(ap, lo2(q2), x2[s][4]);
            x2[s][5] = ffma2(ap, hi2(q2), x2[s][5]);
            x2[s][6] = ffma2(ap, lo2(q3), x2[s][6]);
            x2[s][7] = ffma2(ap, hi2(q3), x2[s][7]);
        }
    }
#pragma unroll
    for (int s = 0; s < NS; s++)
#pragma unroll
        for (int q = 0; q < 4; q++)
            xS[s][n*4+q] = make_float4(x2[s][2*q].x, x2[s][2*q].y, x2[s][2*q+1].x, x2[s][2*q+1].y);
    __syncthreads();

    // ---- 4 GIN layers (single x buffer: sync after reads, sync after write) ----
#pragma unroll
    for (int l = 0; l < 4; l++) {
        float2 nb2[NS][8];
#pragma unroll
        for (int s = 0; s < NS; s++)
#pragma unroll
            for (int j = 0; j < 8; j++) nb2[s][j] = make_float2(0.f, 0.f);
#pragma unroll
        for (int m = 0; m < 13; m++) {
            int o = n * 13 + m;
#pragma unroll
            for (int s = 0; s < NS; s++) {
                float a0 = adjS[s][o], a1 = adjS[s][169+o], a2 = adjS[s][338+o], a3 = adjS[s][507+o];
                float2 g0 = make_float2(a0,a0), g1 = make_float2(a1,a1);
                float2 g2 = make_float2(a2,a2), g3 = make_float2(a3,a3);
                float4 m0 = xS[s][m*4+0], m1 = xS[s][m*4+1], m2 = xS[s][m*4+2], m3 = xS[s][m*4+3];
                nb2[s][0] = ffma2(g0, lo2(m0), nb2[s][0]);  nb2[s][1] = ffma2(g0, hi2(m0), nb2[s][1]);
                nb2[s][2] = ffma2(g1, lo2(m1), nb2[s][2]);  nb2[s][3] = ffma2(g1, hi2(m1), nb2[s][3]);
                nb2[s][4] = ffma2(g2, lo2(m2), nb2[s][4]);  nb2[s][5] = ffma2(g2, hi2(m2), nb2[s][5]);
                nb2[s][6] = ffma2(g3, lo2(m3), nb2[s][6]);  nb2[s][7] = ffma2(g3, hi2(m3), nb2[s][7]);
            }
        }
        if (l < 3) __syncthreads();   // all x reads done before rewrite below
        float e = eps1[l];
        float2 ep = make_float2(e, e);
        float2 agg[NS][8];
#pragma unroll
        for (int s = 0; s < NS; s++)
#pragma unroll
            for (int j = 0; j < 8; j++) agg[s][j] = ffma2(ep, x2[s][j], nb2[s][j]);

        // h1 = agg @ w0^T + b0 -> BN_in -> leaky
        float2 h2[NS][8];
#pragma unroll
        for (int s = 0; s < NS; s++) load8s(h2[s], &b0q[l*4]);
        mm16q(h2, agg, &w0q[l * 64]);
        {
            float2 st = bninq[l * 13 + n];
            float2 sp = make_float2(st.x, st.x), tp = make_float2(st.y, st.y);
#pragma unroll
            for (int s = 0; s < NS; s++)
#pragma unroll
                for (int j = 0; j < 8; j++) {
                    h2[s][j] = ffma2(sp, h2[s][j], tp);
                    h2[s][j].x = lky(h2[s][j].x); h2[s][j].y = lky(h2[s][j].y);
                }
        }
        // out = h1 @ w1^T + b1 -> BN_out -> leaky -> new x
        float2 o2[NS][8];
#pragma unroll
        for (int s = 0; s < NS; s++) load8s(o2[s], &b1q[l*4]);
        mm16q(o2, h2, &w1q[l * 64]);
        {
            float2 st = bnoutq[l * 13 + n];
            float2 sp = make_float2(st.x, st.x), tp = make_float2(st.y, st.y);
#pragma unroll
            for (int s = 0; s < NS; s++)
#pragma unroll
                for (int j = 0; j < 8; j++) {
                    o2[s][j] = ffma2(sp, o2[s][j], tp);
                    o2[s][j].x = lky(o2[s][j].x); o2[s][j].y = lky(o2[s][j].y);
                    x2[s][j] = o2[s][j];
                }
        }
        if (l < 3) {
#pragma unroll
            for (int s = 0; s < NS; s++)
#pragma unroll
                for (int q = 0; q < 4; q++)
                    xS[s][n*4+q] = make_float4(x2[s][2*q].x, x2[s][2*q].y, x2[s][2*q+1].x, x2[s][2*q+1].y);
            __syncthreads();
        }
    }

    // ---- fc heads: logvar first (write+release), then mu (kept for decoder) ----
    {
        float2 lv[NS][8];
#pragma unroll
        for (int s = 0; s < NS; s++) load8s(lv[s], fc2bq);
        mm16q(lv, x2, fc2q);
#pragma unroll
        for (int s = 0; s < NS; s++) {
            size_t bg = (size_t)blockIdx.x * NB + bl + 4 * s;
            float* lvo = d_out + 28966912ull + (bg * 13 + n) * 16;
#pragma unroll
            for (int q = 0; q < 4; q++)
                ((float4*)lvo)[q] = make_float4(lv[s][2*q].x, lv[s][2*q].y, lv[s][2*q+1].x, lv[s][2*q+1].y);
        }
    }
    float2 mu[NS][8];
#pragma unroll
    for (int s = 0; s < NS; s++) load8s(mu[s], fc1bq);
    mm16q(mu, x2, fc1q);
#pragma unroll
    for (int s = 0; s < NS; s++) {
        size_t bg = (size_t)blockIdx.x * NB + bl + 4 * s;
        float* muo = d_out + 22151168ull + (bg * 13 + n) * 16;
#pragma unroll
        for (int q = 0; q < 4; q++)
            ((float4*)muo)[q] = make_float4(mu[s][2*q].x, mu[s][2*q].y, mu[s][2*q+1].x, mu[s][2*q+1].y);
    }

    // Fence: layer-3 adj + x reads complete before t/recon overlay
    __syncthreads();

    // ---- decoder + gram, per-k (t at [0,832), recon at [832,3536)) ----
#pragma unroll
    for (int k = 0; k < 4; k++) {
        if (k) __syncthreads();        // prior k's gram reads of t done
        float2 aa[NS][8];
#pragma unroll
        for (int s = 0; s < NS; s++) load8s(aa[s], &decbq[k*4]);
        mm16q(aa, mu, &decq[k * 64]);
#pragma unroll
        for (int s = 0; s < NS; s++) {
            float4* tS = (float4*)arS[s];
#pragma unroll
            for (int q = 0; q < 4; q++)
                tS[n*4 + q] = make_float4(aa[s][2*q].x, aa[s][2*q].y, aa[s][2*q+1].x, aa[s][2*q+1].y);
        }
        __syncthreads();
        // symmetric gram: tn stays in registers (aa); read rows m<n; mirror
#pragma unroll
        for (int s = 0; s < NS; s++) {
            const float4* tS = (const float4*)arS[s];
            float* rS = (float*)(arS[s] + 832);   // [k*169 + n*13 + m]
            for (int m = 0; m < n; m++) {
                float4 q0 = tS[m*4+0], q1 = tS[m*4+1], q2 = tS[m*4+2], q3 = tS[m*4+3];
                float2 acc = make_float2(0.f, 0.f);
                acc = ffma2(aa[s][0], lo2(q0), acc);  acc = ffma2(aa[s][1], hi2(q0), acc);
                acc = ffma2(aa[s][2], lo2(q1), acc);  acc = ffma2(aa[s][3], hi2(q1), acc);
                acc = ffma2(aa[s][4], lo2(q2), acc);  acc = ffma2(aa[s][5], hi2(q2), acc);
                acc = ffma2(aa[s][6], lo2(q3), acc);  acc = ffma2(aa[s][7], hi2(q3), acc);
                float v = fmaxf(acc.x + acc.y, 0.0f);
                rS[k * 169 + n * 13 + m] = v;
                rS[k * 169 + m * 13 + n] = v;
            }
            // diagonal from registers only
            float2 acc = make_float2(0.f, 0.f);
#pragma unroll
            for (int j = 0; j < 8; j++) acc = ffma2(aa[s][j], aa[s][j], acc);
            rS[k * 169 + n * 13 + n] = fmaxf(acc.x + acc.y, 0.0f);
        }
    }
    __syncthreads();

    // ---- coalesced recon flush (float4) ----
    {
        float4* outg = (float4*)d_out;
        size_t base4 = (size_t)blockIdx.x * NB * 169;
        for (int i = t; i < NB * 169; i += TPB) {       // 52 iters exactly
            int b = i / 169, q = i - b * 169;
            outg[base4 + i] = *(const float4*)(arenas + b * ARENA_BYTES + 832 + q * 16);
        }
    }
}

extern "C" void kernel_launch(void* const* d_in, const int* in_sizes, int n_in,
                              void* d_out, int out_size) {
    (void)in_sizes; (void)n_in; (void)out_size;
    cudaFuncSetAttribute(vae_kernel, cudaFuncAttributeMaxDynamicSharedMemorySize, SMEM_TOTAL);
    vae_kernel<<<NGRID, TPB, SMEM_TOTAL>>>(
        (const float*)d_in[0],  (const float*)d_in[1],  (const float*)d_in[2],
        (const float*)d_in[3],  (const float*)d_in[4],  (const float*)d_in[5],
        (const float*)d_in[6],  (const float*)d_in[7],  (const float*)d_in[8],
        (const float*)d_in[9],  (const float*)d_in[10], (const float*)d_in[11],
        (const float*)d_in[12], (const float*)d_in[13], (const float*)d_in[14],
        (const float*)d_in[15], (const float*)d_in[16], (const float*)d_in[17],
        (const float*)d_in[18], (const float*)d_in[19], (const float*)d_in[20],
        (float*)d_out);
}

// round 13
// speedup vs baseline: 1.4594x; 1.4594x over previous
#include <cuda_runtime.h>

#define TPB 112        // 16 batch elems * 7 threads; each thread does 2 NODES
#define NB  16         // batch elems per block
#define NGRID 2048     // 32768 / 16

#define ARENA_BYTES 3536
#define WREG_BYTES  16912
#define SMEM_TOTAL  (WREG_BYTES + NB * ARENA_BYTES)   // 73488 -> 3 CTAs/SM

// packed f32x2 FMA (sm_100+): r = a*b + c per 32-bit half
__device__ __forceinline__ float2 ffma2(float2 a, float2 b, float2 c) {
    unsigned long long ua = *reinterpret_cast<unsigned long long*>(&a);
    unsigned long long ub = *reinterpret_cast<unsigned long long*>(&b);
    unsigned long long uc = *reinterpret_cast<unsigned long long*>(&c);
    unsigned long long ur;
    asm("fma.rn.f32x2 %0, %1, %2, %3;" : "=l"(ur) : "l"(ua), "l"(ub), "l"(uc));
    return *reinterpret_cast<float2*>(&ur);
}

__device__ __forceinline__ float2 lo2(float4 v) { return make_float2(v.x, v.y); }
__device__ __forceinline__ float2 hi2(float4 v) { return make_float2(v.z, v.w); }

__device__ __forceinline__ float getf2(const float2* v, int d) {
    return (d & 1) ? v[d >> 1].y : v[d >> 1].x;
}

__device__ __forceinline__ float lky(float v) { return fmaxf(v, 0.01f * v); }

// dual 16x16 matmul: one weight read feeds BOTH node streams
__device__ __forceinline__ void mm16d(float2* oa, float2* ob,
                                      const float2* ia, const float2* ib,
                                      const float4* Wq) {
#pragma unroll
    for (int d = 0; d < 16; d++) {
        float av = getf2(ia, d), bv = getf2(ib, d);
        float2 ap = make_float2(av, av), bp = make_float2(bv, bv);
        float4 q0 = Wq[d * 4 + 0];
        float4 q1 = Wq[d * 4 + 1];
        float4 q2 = Wq[d * 4 + 2];
        float4 q3 = Wq[d * 4 + 3];
        oa[0] = ffma2(ap, lo2(q0), oa[0]);  ob[0] = ffma2(bp, lo2(q0), ob[0]);
        oa[1] = ffma2(ap, hi2(q0), oa[1]);  ob[1] = ffma2(bp, hi2(q0), ob[1]);
        oa[2] = ffma2(ap, lo2(q1), oa[2]);  ob[2] = ffma2(bp, lo2(q1), ob[2]);
        oa[3] = ffma2(ap, hi2(q1), oa[3]);  ob[3] = ffma2(bp, hi2(q1), ob[3]);
        oa[4] = ffma2(ap, lo2(q2), oa[4]);  ob[4] = ffma2(bp, lo2(q2), ob[4]);
        oa[5] = ffma2(ap, hi2(q2), oa[5]);  ob[5] = ffma2(bp, hi2(q2), ob[5]);
        oa[6] = ffma2(ap, lo2(q3), oa[6]);  ob[6] = ffma2(bp, lo2(q3), ob[6]);
        oa[7] = ffma2(ap, hi2(q3), oa[7]);  ob[7] = ffma2(bp, hi2(q3), ob[7]);
    }
}

__device__ __forceinline__ void load8s(float2* dst, const float4* src) {
    float4 c0 = src[0], c1 = src[1], c2 = src[2], c3 = src[3];
    dst[0] = lo2(c0); dst[1] = hi2(c0); dst[2] = lo2(c1); dst[3] = hi2(c1);
    dst[4] = lo2(c2); dst[5] = hi2(c2); dst[6] = lo2(c3); dst[7] = hi2(c3);
}

__device__ __forceinline__ float dot16(const float2* a, const float4* row) {
    float2 acc = make_float2(0.f, 0.f);
    acc = ffma2(a[0], lo2(row[0]), acc);  acc = ffma2(a[1], hi2(row[0]), acc);
    acc = ffma2(a[2], lo2(row[1]), acc);  acc = ffma2(a[3], hi2(row[1]), acc);
    acc = ffma2(a[4], lo2(row[2]), acc);  acc = ffma2(a[5], hi2(row[2]), acc);
    acc = ffma2(a[6], lo2(row[3]), acc);  acc = ffma2(a[7], hi2(row[3]), acc);
    return acc.x + acc.y;
}

__global__ __launch_bounds__(TPB, 3)
void vae_kernel(
    const float* __restrict__ adj,          // (B,4,13,13)
    const float* __restrict__ init_weight,  // (13,16)
    const float* __restrict__ eps_param,    // (4)
    const float* __restrict__ mlp_w0,       // (4,16,16)
    const float* __restrict__ mlp_b0,       // (4,16)
    const float* __restrict__ mlp_w1,       // (4,16,16)
    const float* __restrict__ mlp_b1,       // (4,16)
    const float* __restrict__ bn_in_gamma,  // (4,13)
    const float* __restrict__ bn_in_beta,
    const float* __restrict__ bn_in_mean,
    const float* __restrict__ bn_in_var,
    const float* __restrict__ bn_out_gamma,
    const float* __restrict__ bn_out_beta,
    const float* __restrict__ bn_out_mean,
    const float* __restrict__ bn_out_var,
    const float* __restrict__ fc1_w,        // (16,16)
    const float* __restrict__ fc1_b,        // (16)
    const float* __restrict__ fc2_w,
    const float* __restrict__ fc2_b,
    const float* __restrict__ dec_w,        // (4,16,16)
    const float* __restrict__ dec_b,        // (4,16)
    float* __restrict__ d_out)
{
    extern __shared__ char sm[];
    float4* w0q   = (float4*)(sm + 0);      // [4][16][4]
    float4* w1q   = (float4*)(sm + 4096);   // [4][16][4]
    float4* decq  = (float4*)(sm + 8192);   // [4][16][4]
    float4* fc1q  = (float4*)(sm + 12288);  // [16][4]
    float4* fc2q  = (float4*)(sm + 13312);  // [16][4]
    float4* b0q   = (float4*)(sm + 14336);  // [4][4]
    float4* b1q   = (float4*)(sm + 14592);  // [4][4]
    float4* decbq = (float4*)(sm + 14848);  // [4][4]
    float4* fc1bq = (float4*)(sm + 15104);  // [4]
    float4* fc2bq = (float4*)(sm + 15168);  // [4]
    float2* bninq = (float2*)(sm + 15232);  // [4][13] (s,t)
    float2* bnoutq= (float2*)(sm + 15648);  // [4][13] (s,t)
    float4* winitq= (float4*)(sm + 16064);  // [13][4]
    float*  eps1  = (float*)(sm + 16896);   // [4]
    char*   arenas = sm + WREG_BYTES;

    const int t = threadIdx.x;

    // ---- stage transposed/packed weights ----
    for (int idx = t; idx < 256; idx += TPB) {          // 4*16*4
        int l = idx >> 6, d = (idx >> 2) & 15, q = idx & 3;
        const float* w  = mlp_w0 + l * 256;
        const float* w1 = mlp_w1 + l * 256;
        const float* dw = dec_w  + l * 256;
        w0q[idx]  = make_float4(w [(4*q+0)*16+d], w [(4*q+1)*16+d], w [(4*q+2)*16+d], w [(4*q+3)*16+d]);
        w1q[idx]  = make_float4(w1[(4*q+0)*16+d], w1[(4*q+1)*16+d], w1[(4*q+2)*16+d], w1[(4*q+3)*16+d]);
        decq[idx] = make_float4(dw[(4*q+0)*16+d], dw[(4*q+1)*16+d], dw[(4*q+2)*16+d], dw[(4*q+3)*16+d]);
    }
    for (int idx = t; idx < 64; idx += TPB) {           // 16*4
        int d = idx >> 2, q = idx & 3;
        fc1q[idx] = make_float4(fc1_w[(4*q+0)*16+d], fc1_w[(4*q+1)*16+d], fc1_w[(4*q+2)*16+d], fc1_w[(4*q+3)*16+d]);
        fc2q[idx] = make_float4(fc2_w[(4*q+0)*16+d], fc2_w[(4*q+1)*16+d], fc2_w[(4*q+2)*16+d], fc2_w[(4*q+3)*16+d]);
    }
    for (int idx = t; idx < 52; idx += TPB)             // 13*4
        winitq[idx] = ((const float4*)init_weight)[idx];
    for (int idx = t; idx < 16; idx += TPB) {           // 4*4
        b0q[idx]   = ((const float4*)mlp_b0)[idx];
        b1q[idx]   = ((const float4*)mlp_b1)[idx];
        decbq[idx] = ((const float4*)dec_b)[idx];
    }
    if (t < 4) {
        fc1bq[t] = ((const float4*)fc1_b)[t];
        fc2bq[t] = ((const float4*)fc2_b)[t];
        eps1[t]  = 1.0f + eps_param[t];
    }
    for (int idx = t; idx < 52; idx += TPB) {           // 4*13 BN fold
        float s = bn_in_gamma[idx] * rsqrtf(bn_in_var[idx] + 1e-5f);
        bninq[idx] = make_float2(s, bn_in_beta[idx] - bn_in_mean[idx] * s);
        float so = bn_out_gamma[idx] * rsqrtf(bn_out_var[idx] + 1e-5f);
        bnoutq[idx] = make_float2(so, bn_out_beta[idx] - bn_out_mean[idx] * so);
    }

    // ---- load adj (coalesced float4) into per-b arenas ----
    const float4* adjg = (const float4*)(adj + (size_t)blockIdx.x * NB * 676);
    for (int i = t; i < NB * 169; i += TPB) {
        int b = i / 169, q = i - b * 169;
        *(float4*)(arenas + b * ARENA_BYTES + q * 16) = adjg[i];
    }
    __syncthreads();

    // ---- per-thread: (bl, i) handles nodes n1=i, n2=(i+7)%13 of ONE batch elem ----
    const int bl = t / 7;
    const int i7 = t - bl * 7;
    const int n1 = i7;
    const int n2 = (i7 + 7) % 13;   // thread 6 -> node 0 (duplicate, identical math)
    char*   ar   = arenas + bl * ARENA_BYTES;
    float*  adjS = (float*)ar;                 // [g*169 + n*13 + m]
    float4* xS   = (float4*)(ar + 2704);       // [13][4] single buffer

    // ---- x init (both nodes) ----
    float2 x2[2][8];
#pragma unroll
    for (int s = 0; s < 2; s++)
#pragma unroll
        for (int j = 0; j < 8; j++) x2[s][j] = make_float2(0.f, 0.f);
#pragma unroll
    for (int m = 0; m < 13; m++) {
        int o1 = n1 * 13 + m, o2 = n2 * 13 + m;
        float sa = adjS[o1] + adjS[169 + o1] + adjS[338 + o1] + adjS[507 + o1];
        float sb = adjS[o2] + adjS[169 + o2] + adjS[338 + o2] + adjS[507 + o2];
        float2 ap = make_float2(sa, sa), bp = make_float2(sb, sb);
        float4 q0 = winitq[m*4+0], q1 = winitq[m*4+1], q2 = winitq[m*4+2], q3 = winitq[m*4+3];
        x2[0][0] = ffma2(ap, lo2(q0), x2[0][0]);  x2[1][0] = ffma2(bp, lo2(q0), x2[1][0]);
        x2[0][1] = ffma2(ap, hi2(q0), x2[0][1]);  x2[1][1] = ffma2(bp, hi2(q0), x2[1][1]);
        x2[0][2] = ffma2(ap, lo2(q1), x2[0][2]);  x2[1][2] = ffma2(bp, lo2(q1), x2[1][2]);
        x2[0][3] = ffma2(ap, hi2(q1), x2[0][3]);  x2[1][3] = ffma2(bp, hi2(q1), x2[1][3]);
        x2[0][4] = ffma2(ap, lo2(q2), x2[0][4]);  x2[1][4] = ffma2(bp, lo2(q2), x2[1][4]);
        x2[0][5] = ffma2(ap, hi2(q2), x2[0][5]);  x2[1][5] = ffma2(bp, hi2(q2), x2[1][5]);
        x2[0][6] = ffma2(ap, lo2(q3), x2[0][6]);  x2[1][6] = ffma2(bp, lo2(q3), x2[1][6]);
        x2[0][7] = ffma2(ap, hi2(q3), x2[0][7]);  x2[1][7] = ffma2(bp, hi2(q3), x2[1][7]);
    }
#pragma unroll
    for (int q = 0; q < 4; q++) {
        xS[n1*4+q] = make_float4(x2[0][2*q].x, x2[0][2*q].y, x2[0][2*q+1].x, x2[0][2*q+1].y);
        xS[n2*4+q] = make_float4(x2[1][2*q].x, x2[1][2*q].y, x2[1][2*q+1].x, x2[1][2*q+1].y);
    }
    __syncthreads();

    // ---- 4 GIN layers: x row m read ONCE, feeds both node accumulators ----
#pragma unroll
    for (int l = 0; l < 4; l++) {
        float2 nb2[2][8];
#pragma unroll
        for (int s = 0; s < 2; s++)
#pragma unroll
            for (int j = 0; j < 8; j++) nb2[s][j] = make_float2(0.f, 0.f);
#pragma unroll
        for (int m = 0; m < 13; m++) {
            float4 m0 = xS[m*4+0], m1 = xS[m*4+1], m2 = xS[m*4+2], m3 = xS[m*4+3];
            int o1 = n1 * 13 + m, o2 = n2 * 13 + m;
            {
                float a0 = adjS[o1], a1 = adjS[169+o1], a2 = adjS[338+o1], a3 = adjS[507+o1];
                float2 g0 = make_float2(a0,a0), g1 = make_float2(a1,a1);
                float2 g2 = make_float2(a2,a2), g3 = make_float2(a3,a3);
                nb2[0][0] = ffma2(g0, lo2(m0), nb2[0][0]);  nb2[0][1] = ffma2(g0, hi2(m0), nb2[0][1]);
                nb2[0][2] = ffma2(g1, lo2(m1), nb2[0][2]);  nb2[0][3] = ffma2(g1, hi2(m1), nb2[0][3]);
                nb2[0][4] = ffma2(g2, lo2(m2), nb2[0][4]);  nb2[0][5] = ffma2(g2, hi2(m2), nb2[0][5]);
                nb2[0][6] = ffma2(g3, lo2(m3), nb2[0][6]);  nb2[0][7] = ffma2(g3, hi2(m3), nb2[0][7]);
            }
            {
                float a0 = adjS[o2], a1 = adjS[169+o2], a2 = adjS[338+o2], a3 = adjS[507+o2];
                float2 g0 = make_float2(a0,a0), g1 = make_float2(a1,a1);
                float2 g2 = make_float2(a2,a2), g3 = make_float2(a3,a3);
                nb2[1][0] = ffma2(g0, lo2(m0), nb2[1][0]);  nb2[1][1] = ffma2(g0, hi2(m0), nb2[1][1]);
                nb2[1][2] = ffma2(g1, lo2(m1), nb2[1][2]);  nb2[1][3] = ffma2(g1, hi2(m1), nb2[1][3]);
                nb2[1][4] = ffma2(g2, lo2(m2), nb2[1][4]);  nb2[1][5] = ffma2(g2, hi2(m2), nb2[1][5]);
                nb2[1][6] = ffma2(g3, lo2(m3), nb2[1][6]);  nb2[1][7] = ffma2(g3, hi2(m3), nb2[1][7]);
            }
        }
        if (l < 3) __syncthreads();   // all x reads done before rewrite below
        float e = eps1[l];
        float2 ep = make_float2(e, e);
        float2 agg[2][8];
#pragma unroll
        for (int s = 0; s < 2; s++)
#pragma unroll
            for (int j = 0; j < 8; j++) agg[s][j] = ffma2(ep, x2[s][j], nb2[s][j]);

        // h1 = agg @ w0^T + b0 -> BN_in -> leaky
        float2 h2[2][8];
        load8s(h2[0], &b0q[l*4]);
#pragma unroll
        for (int j = 0; j < 8; j++) h2[1][j] = h2[0][j];
        mm16d(h2[0], h2[1], agg[0], agg[1], &w0q[l * 64]);
        {
            float2 s1 = bninq[l * 13 + n1], s2 = bninq[l * 13 + n2];
            float2 sp1 = make_float2(s1.x, s1.x), tp1 = make_float2(s1.y, s1.y);
            float2 sp2 = make_float2(s2.x, s2.x), tp2 = make_float2(s2.y, s2.y);
#pragma unroll
            for (int j = 0; j < 8; j++) {
                h2[0][j] = ffma2(sp1, h2[0][j], tp1);
                h2[0][j].x = lky(h2[0][j].x); h2[0][j].y = lky(h2[0][j].y);
                h2[1][j] = ffma2(sp2, h2[1][j], tp2);
                h2[1][j].x = lky(h2[1][j].x); h2[1][j].y = lky(h2[1][j].y);
            }
        }
        // out = h1 @ w1^T + b1 -> BN_out -> leaky -> new x
        float2 o2[2][8];
        load8s(o2[0], &b1q[l*4]);
#pragma unroll
        for (int j = 0; j < 8; j++) o2[1][j] = o2[0][j];
        mm16d(o2[0], o2[1], h2[0], h2[1], &w1q[l * 64]);
        {
            float2 s1 = bnoutq[l * 13 + n1], s2 = bnoutq[l * 13 + n2];
            float2 sp1 = make_float2(s1.x, s1.x), tp1 = make_float2(s1.y, s1.y);
            float2 sp2 = make_float2(s2.x, s2.x), tp2 = make_float2(s2.y, s2.y);
#pragma unroll
            for (int j = 0; j < 8; j++) {
                o2[0][j] = ffma2(sp1, o2[0][j], tp1);
                o2[0][j].x = lky(o2[0][j].x); o2[0][j].y = lky(o2[0][j].y);
                x2[0][j] = o2[0][j];
                o2[1][j] = ffma2(sp2, o2[1][j], tp2);
                o2[1][j].x = lky(o2[1][j].x); o2[1][j].y = lky(o2[1][j].y);
                x2[1][j] = o2[1][j];
            }
        }
        if (l < 3) {
#pragma unroll
            for (int q = 0; q < 4; q++) {
                xS[n1*4+q] = make_float4(x2[0][2*q].x, x2[0][2*q].y, x2[0][2*q+1].x, x2[0][2*q+1].y);
                xS[n2*4+q] = make_float4(x2[1][2*q].x, x2[1][2*q].y, x2[1][2*q+1].x, x2[1][2*q+1].y);
            }
            __syncthreads();
        }
    }

    // ---- fc heads: logvar (write+release), then mu (kept for decoder) ----
    {
        size_t bg = (size_t)blockIdx.x * NB + bl;
        float2 lv[2][8];
        load8s(lv[0], fc2bq);
#pragma unroll
        for (int j = 0; j < 8; j++) lv[1][j] = lv[0][j];
        mm16d(lv[0], lv[1], x2[0], x2[1], fc2q);
        float* lvo1 = d_out + 28966912ull + (bg * 13 + n1) * 16;
        float* lvo2 = d_out + 28966912ull + (bg * 13 + n2) * 16;
#pragma unroll
        for (int q = 0; q < 4; q++) {
            ((float4*)lvo1)[q] = make_float4(lv[0][2*q].x, lv[0][2*q].y, lv[0][2*q+1].x, lv[0][2*q+1].y);
            ((float4*)lvo2)[q] = make_float4(lv[1][2*q].x, lv[1][2*q].y, lv[1][2*q+1].x, lv[1][2*q+1].y);
        }
    }
    float2 mu[2][8];
    load8s(mu[0], fc1bq);
#pragma unroll
    for (int j = 0; j < 8; j++) mu[1][j] = mu[0][j];
    mm16d(mu[0], mu[1], x2[0], x2[1], fc1q);
    {
        size_t bg = (size_t)blockIdx.x * NB + bl;
        float* muo1 = d_out + 22151168ull + (bg * 13 + n1) * 16;
        float* muo2 = d_out + 22151168ull + (bg * 13 + n2) * 16;
#pragma unroll
        for (int q = 0; q < 4; q++) {
            ((float4*)muo1)[q] = make_float4(mu[0][2*q].x, mu[0][2*q].y, mu[0][2*q+1].x, mu[0][2*q+1].y);
            ((float4*)muo2)[q] = make_float4(mu[1][2*q].x, mu[1][2*q].y, mu[1][2*q+1].x, mu[1][2*q+1].y);
        }
    }

    // Fence: layer-3 adj + x reads complete before t/recon overlay
    __syncthreads();

    // ---- decoder + gram, per-k (t at [0,832), recon at [832,3536)) ----
    float4* tS = (float4*)ar;
    float*  rS = (float*)(ar + 832);       // [k*169 + n*13 + m]
    const int nhi = (n2 > n1) ? n2 : n1;   // thread 6: nhi = 6
#pragma unroll
    for (int k = 0; k < 4; k++) {
        if (k) __syncthreads();            // prior k's gram reads of t done
        float2 aa[2][8];
        load8s(aa[0], &decbq[k*4]);
#pragma unroll
        for (int j = 0; j < 8; j++) aa[1][j] = aa[0][j];
        mm16d(aa[0], aa[1], mu[0], mu[1], &decq[k * 64]);
#pragma unroll
        for (int q = 0; q < 4; q++) {
            tS[n1*4 + q] = make_float4(aa[0][2*q].x, aa[0][2*q].y, aa[0][2*q+1].x, aa[0][2*q+1].y);
            tS[n2*4 + q] = make_float4(aa[1][2*q].x, aa[1][2*q].y, aa[1][2*q+1].x, aa[1][2*q+1].y);
        }
        __syncthreads();
        // symmetric gram: row m read once, serves both nodes; diagonals from regs
        for (int m = 0; m < nhi; m++) {
            float4 row[4];
            row[0] = tS[m*4+0]; row[1] = tS[m*4+1]; row[2] = tS[m*4+2]; row[3] = tS[m*4+3];
            if (m < n1) {
                float v = fmaxf(dot16(aa[0], row), 0.0f);
                rS[k * 169 + n1 * 13 + m] = v;
                rS[k * 169 + m * 13 + n1] = v;
            }
            if (m < n2) {
                float v = fmaxf(dot16(aa[1], row), 0.0f);
                rS[k * 169 + n2 * 13 + m] = v;
                rS[k * 169 + m * 13 + n2] = v;
            }
        }
        {
            float2 acc = make_float2(0.f, 0.f);
#pragma unroll
            for (int j = 0; j < 8; j++) acc = ffma2(aa[0][j], aa[0][j], acc);
            rS[k * 169 + n1 * 13 + n1] = fmaxf(acc.x + acc.y, 0.0f);
            float2 acc2 = make_float2(0.f, 0.f);
#pragma unroll
            for (int j = 0; j < 8; j++) acc2 = ffma2(aa[1][j], aa[1][j], acc2);
            rS[k * 169 + n2 * 13 + n2] = fmaxf(acc2.x + acc2.y, 0.0f);
        }
    }
    __syncthreads();

    // ---- coalesced recon flush (float4) ----
    {
        float4* outg = (float4*)d_out;
        size_t base4 = (size_t)blockIdx.x * NB * 169;
        for (int i = t; i < NB * 169; i += TPB) {
            int b = i / 169, q = i - b * 169;
            outg[base4 + i] = *(const float4*)(arenas + b * ARENA_BYTES + 832 + q * 16);
        }
    }
}

extern "C" void kernel_launch(void* const* d_in, const int* in_sizes, int n_in,
                              void* d_out, int out_size) {
    (void)in_sizes; (void)n_in; (void)out_size;
    cudaFuncSetAttribute(vae_kernel, cudaFuncAttributeMaxDynamicSharedMemorySize, SMEM_TOTAL);
    vae_kernel<<<NGRID, TPB, SMEM_TOTAL>>>(
        (const float*)d_in[0],  (const float*)d_in[1],  (const float*)d_in[2],
        (const float*)d_in[3],  (const float*)d_in[4],  (const float*)d_in[5],
        (const float*)d_in[6],  (const float*)d_in[7],  (const float*)d_in[8],
        (const float*)d_in[9],  (const float*)d_in[10], (const float*)d_in[11],
        (const float*)d_in[12], (const float*)d_in[13], (const float*)d_in[14],
        (const float*)d_in[15], (const float*)d_in[16], (const float*)d_in[17],
        (const float*)d_in[18], (const float*)d_in[19], (const float*)d_in[20],
        (float*)d_out);
}